// round 1
// baseline (speedup 1.0000x reference)
#include <cuda_runtime.h>
#include <cuda_bf16.h>
#include <cstdint>

#define H_IMG 256
#define W_IMG 256
#define BATCH 8
#define CIN1  64
#define COUT  128
#define SDIM  64

#define TW 32
#define TH 8
#define COUT_T 32
#define CI_CHUNK 16
#define NTHREADS 256

#define EPSV 1e-8f
#define INV_SQRT2 0.70710678118654752440f

// ---------------- scratch + precomputed small tensors ----------------
__device__ float g_t[(size_t)BATCH * COUT * H_IMG * W_IMG]; // 256 MB intermediate
__device__ float g_style1[BATCH * CIN1];
__device__ float g_style2[BATCH * COUT];
__device__ float g_d1[BATCH * COUT];
__device__ float g_d2[BATCH * COUT];
__device__ float g_d2inv[BATCH * COUT];

__device__ __forceinline__ float lrelu(float v) { return v > 0.f ? v : 0.2f * v; }

// ---------------- k0: styles + demod factors ----------------
__global__ void precompute_kernel(const float* __restrict__ s,
                                  const float* __restrict__ a1w, const float* __restrict__ a1b,
                                  const float* __restrict__ w1,
                                  const float* __restrict__ a2w, const float* __restrict__ a2b,
                                  const float* __restrict__ w2) {
    int b = blockIdx.x;
    int t = threadIdx.x;  // 0..127
    __shared__ float sh_s[SDIM];
    __shared__ float st1[CIN1];
    __shared__ float st2[COUT];

    if (t < SDIM) sh_s[t] = s[b * SDIM + t];
    __syncthreads();

    if (t < CIN1) {
        float acc = a1b[t];
        #pragma unroll 4
        for (int j = 0; j < SDIM; j++) acc += sh_s[j] * a1w[t * SDIM + j];
        acc += 1.0f;
        st1[t] = acc;
        g_style1[b * CIN1 + t] = acc;
    }
    {
        float acc = a2b[t];
        #pragma unroll 4
        for (int j = 0; j < SDIM; j++) acc += sh_s[j] * a2w[t * SDIM + j];
        acc += 1.0f;
        st2[t] = acc;
        g_style2[b * COUT + t] = acc;
    }
    __syncthreads();

    // d1[b][t] over w1 [128][64][9]
    {
        float sum = 0.f;
        for (int i = 0; i < CIN1; i++) {
            float wsq = 0.f;
            #pragma unroll
            for (int k = 0; k < 9; k++) { float wv = w1[(t * CIN1 + i) * 9 + k]; wsq += wv * wv; }
            float sv = st1[i];
            sum += wsq * sv * sv;
        }
        g_d1[b * COUT + t] = rsqrtf(sum + EPSV);
    }
    // d2[b][t] over w2 [128][128][9]
    {
        float sum = 0.f;
        for (int i = 0; i < COUT; i++) {
            float wsq = 0.f;
            #pragma unroll
            for (int k = 0; k < 9; k++) { float wv = w2[(t * COUT + i) * 9 + k]; wsq += wv * wv; }
            float sv = st2[i];
            sum += wsq * sv * sv;
        }
        float d = rsqrtf(sum + EPSV);
        g_d2[b * COUT + t] = d;
        g_d2inv[b * COUT + t] = 1.0f / d;
    }
}

// ---------------- fused 3x3 conv kernel ----------------
// FIRST:  in = x, apply lrelu+style1 on load; epilogue -> g_t = style2*lrelu(d1*acc + nw*noise)
// !FIRST: in = g_t; extra 1x1 shortcut (weights pre-divided by d2); epilogue ->
//         out = (d2*acc + nw*noise) * INV_SQRT2
template <int CIN, bool FIRST>
__global__ __launch_bounds__(NTHREADS)
void conv3x3_kernel(const float* __restrict__ in_x,       // x for FIRST / shortcut source for second
                    const float* __restrict__ w,
                    const float* __restrict__ noise,
                    const float* __restrict__ noise_w,
                    const float* __restrict__ scw,        // only used when !FIRST
                    float* __restrict__ out) {
    __shared__ __align__(16) float s_in[CI_CHUNK][TH + 2][36];
    __shared__ __align__(16) float s_w[CI_CHUNK][9][36];

    const int tid = threadIdx.x;
    const int cg  = tid & 7;        // 8 cout subgroups of 4
    const int cg4 = cg * 4;
    const int pt  = tid >> 3;       // 0..31
    const int ty  = pt >> 2;        // 0..7
    const int tx0 = (pt & 3) * 8;   // 0,8,16,24

    const int bz  = blockIdx.z;
    const int b   = bz >> 2;
    const int co0 = (bz & 3) * COUT_T;
    const int oy0 = blockIdx.y * TH;
    const int ox0 = blockIdx.x * TW;

    const float* inp = FIRST ? in_x : (const float*)g_t;

    float acc[8][4];
    #pragma unroll
    for (int m = 0; m < 8; m++)
        #pragma unroll
        for (int j = 0; j < 4; j++) acc[m][j] = 0.f;

    for (int ci0 = 0; ci0 < CIN; ci0 += CI_CHUNK) {
        __syncthreads();
        // ---- input tile (with halo) ----
        const float* in_b = inp + ((size_t)b * CIN + ci0) * (H_IMG * W_IMG);
        for (int idx = tid; idx < CI_CHUNK * 10 * 34; idx += NTHREADS) {
            int ci = idx / 340;
            int r  = idx - ci * 340;
            int yy = r / 34;
            int xx = r - yy * 34;
            int gy = oy0 - 1 + yy;
            int gx = ox0 - 1 + xx;
            float v = 0.f;
            if ((unsigned)gy < H_IMG && (unsigned)gx < W_IMG)
                v = __ldg(in_b + ci * (H_IMG * W_IMG) + gy * W_IMG + gx);
            if (FIRST) v = lrelu(v) * g_style1[b * CIN1 + ci0 + ci];
            s_in[ci][yy][xx] = v;
        }
        // ---- weights (coalesced over ci*9, 4-way STS conflict is negligible) ----
        const float* w_b = w + ((size_t)co0 * CIN + ci0) * 9;
        for (int idx = tid; idx < CI_CHUNK * 9 * COUT_T; idx += NTHREADS) {
            int co = idx / (CI_CHUNK * 9);
            int rk = idx - co * (CI_CHUNK * 9);   // ci*9 + k
            int ci = rk / 9;
            int k  = rk - ci * 9;
            s_w[ci][k][co] = __ldg(w_b + (size_t)co * CIN * 9 + rk);
        }
        __syncthreads();

        #pragma unroll 1
        for (int ci = 0; ci < CI_CHUNK; ci++) {
            #pragma unroll
            for (int kh = 0; kh < 3; kh++) {
                const float* row = &s_in[ci][ty + kh][tx0];
                float4 ra = *(const float4*)(row);
                float4 rb = *(const float4*)(row + 4);
                float2 rc = *(const float2*)(row + 8);
                float r[10] = {ra.x, ra.y, ra.z, ra.w, rb.x, rb.y, rb.z, rb.w, rc.x, rc.y};
                #pragma unroll
                for (int kw = 0; kw < 3; kw++) {
                    float4 wv = *(const float4*)&s_w[ci][kh * 3 + kw][cg4];
                    #pragma unroll
                    for (int m = 0; m < 8; m++) {
                        float iv = r[m + kw];
                        acc[m][0] += iv * wv.x;
                        acc[m][1] += iv * wv.y;
                        acc[m][2] += iv * wv.z;
                        acc[m][3] += iv * wv.w;
                    }
                }
            }
        }
    }

    if (!FIRST) {
        // ---- 1x1 learned shortcut on raw x, weights pre-scaled by 1/d2 ----
        for (int sc0 = 0; sc0 < CIN1; sc0 += CI_CHUNK) {
            __syncthreads();
            for (int idx = tid; idx < CI_CHUNK * TH * TW; idx += NTHREADS) {
                int ci = idx >> 8;
                int r  = idx & 255;
                int yy = r >> 5;
                int xx = r & 31;
                s_in[ci][yy + 1][xx + 1] =
                    __ldg(in_x + (((size_t)b * CIN1 + sc0 + ci) * H_IMG + oy0 + yy) * W_IMG + ox0 + xx);
            }
            for (int idx = tid; idx < CI_CHUNK * COUT_T; idx += NTHREADS) {
                int co = idx >> 4;
                int ci = idx & 15;
                s_w[ci][0][co] = __ldg(scw + (size_t)(co0 + co) * CIN1 + sc0 + ci)
                                 * g_d2inv[b * COUT + co0 + co];
            }
            __syncthreads();
            #pragma unroll 1
            for (int ci = 0; ci < CI_CHUNK; ci++) {
                float4 wv = *(const float4*)&s_w[ci][0][cg4];
                const float* rowp = &s_in[ci][ty + 1][tx0 + 1];
                #pragma unroll
                for (int m = 0; m < 8; m++) {
                    float iv = rowp[m];
                    acc[m][0] += iv * wv.x;
                    acc[m][1] += iv * wv.y;
                    acc[m][2] += iv * wv.z;
                    acc[m][3] += iv * wv.w;
                }
            }
        }
    }

    // ---- epilogue ----
    const int gy  = oy0 + ty;
    const int gx0 = ox0 + tx0;
    const float nw = __ldg(noise_w);
    float nz[8];
    #pragma unroll
    for (int m = 0; m < 8; m++)
        nz[m] = nw * __ldg(noise + (size_t)b * (H_IMG * W_IMG) + gy * W_IMG + gx0 + m);

    #pragma unroll
    for (int j = 0; j < 4; j++) {
        int co = co0 + cg4 + j;
        float vv[8];
        if (FIRST) {
            float dm = g_d1[b * COUT + co];
            float st = g_style2[b * COUT + co];
            #pragma unroll
            for (int m = 0; m < 8; m++) {
                float v = dm * acc[m][j] + nz[m];
                vv[m] = lrelu(v) * st;
            }
        } else {
            float dm = g_d2[b * COUT + co];
            #pragma unroll
            for (int m = 0; m < 8; m++)
                vv[m] = (dm * acc[m][j] + nz[m]) * INV_SQRT2;
        }
        float* op = (FIRST ? (float*)g_t : out)
                    + ((size_t)b * COUT + co) * (H_IMG * W_IMG) + gy * W_IMG + gx0;
        *(float4*)(op)     = make_float4(vv[0], vv[1], vv[2], vv[3]);
        *(float4*)(op + 4) = make_float4(vv[4], vv[5], vv[6], vv[7]);
    }
}

// ---------------- launch ----------------
extern "C" void kernel_launch(void* const* d_in, const int* in_sizes, int n_in,
                              void* d_out, int out_size) {
    const float* x    = (const float*)d_in[0];
    const float* s    = (const float*)d_in[1];
    const float* noise= (const float*)d_in[2];
    const float* a1w  = (const float*)d_in[3];
    const float* a1b  = (const float*)d_in[4];
    const float* w1   = (const float*)d_in[5];
    const float* a2w  = (const float*)d_in[6];
    const float* a2b  = (const float*)d_in[7];
    const float* w2   = (const float*)d_in[8];
    const float* nw   = (const float*)d_in[9];
    const float* scw  = (const float*)d_in[10];
    float* out = (float*)d_out;

    precompute_kernel<<<BATCH, 128>>>(s, a1w, a1b, w1, a2w, a2b, w2);

    dim3 grid(W_IMG / TW, H_IMG / TH, BATCH * (COUT / COUT_T));
    conv3x3_kernel<CIN1, true><<<grid, NTHREADS>>>(x, w1, noise, nw, nullptr, nullptr);
    conv3x3_kernel<COUT, false><<<grid, NTHREADS>>>(x, w2, noise, nw, scw, out);
}

// round 2
// speedup vs baseline: 1.0003x; 1.0003x over previous
#include <cuda_runtime.h>
#include <cuda_bf16.h>
#include <cstdint>

#define H_IMG 256
#define W_IMG 256
#define BATCH 8
#define CIN1  64
#define COUT  128
#define SDIM  64

#define TW 32
#define TH 8
#define COUT_T 32
#define CI_CHUNK 16
#define NTHREADS 256

#define EPSV 1e-8f
#define INV_SQRT2 0.70710678118654752440f

// ---------------- scratch + precomputed small tensors ----------------
__device__ float g_t[(size_t)BATCH * COUT * H_IMG * W_IMG]; // 256 MB intermediate
__device__ float g_style1[BATCH * CIN1];
__device__ float g_style2[BATCH * COUT];
__device__ float g_d1[BATCH * COUT];
__device__ float g_d2[BATCH * COUT];
__device__ float g_d2inv[BATCH * COUT];

__device__ __forceinline__ float lrelu(float v) { return v > 0.f ? v : 0.2f * v; }

// ---------------- k0: styles + demod factors ----------------
__global__ void precompute_kernel(const float* __restrict__ s,
                                  const float* __restrict__ a1w, const float* __restrict__ a1b,
                                  const float* __restrict__ w1,
                                  const float* __restrict__ a2w, const float* __restrict__ a2b,
                                  const float* __restrict__ w2) {
    int b = blockIdx.x;
    int t = threadIdx.x;  // 0..127
    __shared__ float sh_s[SDIM];
    __shared__ float st1[CIN1];
    __shared__ float st2[COUT];

    if (t < SDIM) sh_s[t] = s[b * SDIM + t];
    __syncthreads();

    if (t < CIN1) {
        float acc = a1b[t];
        #pragma unroll 4
        for (int j = 0; j < SDIM; j++) acc += sh_s[j] * a1w[t * SDIM + j];
        acc += 1.0f;
        st1[t] = acc;
        g_style1[b * CIN1 + t] = acc;
    }
    {
        float acc = a2b[t];
        #pragma unroll 4
        for (int j = 0; j < SDIM; j++) acc += sh_s[j] * a2w[t * SDIM + j];
        acc += 1.0f;
        st2[t] = acc;
        g_style2[b * COUT + t] = acc;
    }
    __syncthreads();

    // d1[b][t] over w1 [128][64][9]
    {
        float sum = 0.f;
        for (int i = 0; i < CIN1; i++) {
            float wsq = 0.f;
            #pragma unroll
            for (int k = 0; k < 9; k++) { float wv = w1[(t * CIN1 + i) * 9 + k]; wsq += wv * wv; }
            float sv = st1[i];
            sum += wsq * sv * sv;
        }
        g_d1[b * COUT + t] = rsqrtf(sum + EPSV);
    }
    // d2[b][t] over w2 [128][128][9]
    {
        float sum = 0.f;
        for (int i = 0; i < COUT; i++) {
            float wsq = 0.f;
            #pragma unroll
            for (int k = 0; k < 9; k++) { float wv = w2[(t * COUT + i) * 9 + k]; wsq += wv * wv; }
            float sv = st2[i];
            sum += wsq * sv * sv;
        }
        float d = rsqrtf(sum + EPSV);
        g_d2[b * COUT + t] = d;
        g_d2inv[b * COUT + t] = 1.0f / d;
    }
}

// ---------------- fused 3x3 conv kernel ----------------
// FIRST:  in = x, apply lrelu+style1 on load; epilogue -> g_t = style2*lrelu(d1*acc + nw*noise)
// !FIRST: in = g_t; extra 1x1 shortcut (weights pre-divided by d2); epilogue ->
//         out = (d2*acc + nw*noise) * INV_SQRT2
template <int CIN, bool FIRST>
__global__ __launch_bounds__(NTHREADS)
void conv3x3_kernel(const float* __restrict__ in_x,       // x for FIRST / shortcut source for second
                    const float* __restrict__ w,
                    const float* __restrict__ noise,
                    const float* __restrict__ noise_w,
                    const float* __restrict__ scw,        // only used when !FIRST
                    float* __restrict__ out) {
    __shared__ __align__(16) float s_in[CI_CHUNK][TH + 2][36];
    __shared__ __align__(16) float s_w[CI_CHUNK][9][36];

    const int tid = threadIdx.x;
    const int cg  = tid & 7;        // 8 cout subgroups of 4
    const int cg4 = cg * 4;
    const int pt  = tid >> 3;       // 0..31
    const int ty  = pt >> 2;        // 0..7
    const int tx0 = (pt & 3) * 8;   // 0,8,16,24

    const int bz  = blockIdx.z;
    const int b   = bz >> 2;
    const int co0 = (bz & 3) * COUT_T;
    const int oy0 = blockIdx.y * TH;
    const int ox0 = blockIdx.x * TW;

    const float* inp = FIRST ? in_x : (const float*)g_t;

    float acc[8][4];
    #pragma unroll
    for (int m = 0; m < 8; m++)
        #pragma unroll
        for (int j = 0; j < 4; j++) acc[m][j] = 0.f;

    for (int ci0 = 0; ci0 < CIN; ci0 += CI_CHUNK) {
        __syncthreads();
        // ---- input tile (with halo) ----
        const float* in_b = inp + ((size_t)b * CIN + ci0) * (H_IMG * W_IMG);
        for (int idx = tid; idx < CI_CHUNK * 10 * 34; idx += NTHREADS) {
            int ci = idx / 340;
            int r  = idx - ci * 340;
            int yy = r / 34;
            int xx = r - yy * 34;
            int gy = oy0 - 1 + yy;
            int gx = ox0 - 1 + xx;
            float v = 0.f;
            if ((unsigned)gy < H_IMG && (unsigned)gx < W_IMG)
                v = __ldg(in_b + ci * (H_IMG * W_IMG) + gy * W_IMG + gx);
            if (FIRST) v = lrelu(v) * g_style1[b * CIN1 + ci0 + ci];
            s_in[ci][yy][xx] = v;
        }
        // ---- weights (coalesced over ci*9, 4-way STS conflict is negligible) ----
        const float* w_b = w + ((size_t)co0 * CIN + ci0) * 9;
        for (int idx = tid; idx < CI_CHUNK * 9 * COUT_T; idx += NTHREADS) {
            int co = idx / (CI_CHUNK * 9);
            int rk = idx - co * (CI_CHUNK * 9);   // ci*9 + k
            int ci = rk / 9;
            int k  = rk - ci * 9;
            s_w[ci][k][co] = __ldg(w_b + (size_t)co * CIN * 9 + rk);
        }
        __syncthreads();

        #pragma unroll 1
        for (int ci = 0; ci < CI_CHUNK; ci++) {
            #pragma unroll
            for (int kh = 0; kh < 3; kh++) {
                const float* row = &s_in[ci][ty + kh][tx0];
                float4 ra = *(const float4*)(row);
                float4 rb = *(const float4*)(row + 4);
                float2 rc = *(const float2*)(row + 8);
                float r[10] = {ra.x, ra.y, ra.z, ra.w, rb.x, rb.y, rb.z, rb.w, rc.x, rc.y};
                #pragma unroll
                for (int kw = 0; kw < 3; kw++) {
                    float4 wv = *(const float4*)&s_w[ci][kh * 3 + kw][cg4];
                    #pragma unroll
                    for (int m = 0; m < 8; m++) {
                        float iv = r[m + kw];
                        acc[m][0] += iv * wv.x;
                        acc[m][1] += iv * wv.y;
                        acc[m][2] += iv * wv.z;
                        acc[m][3] += iv * wv.w;
                    }
                }
            }
        }
    }

    if (!FIRST) {
        // ---- 1x1 learned shortcut on raw x, weights pre-scaled by 1/d2 ----
        for (int sc0 = 0; sc0 < CIN1; sc0 += CI_CHUNK) {
            __syncthreads();
            for (int idx = tid; idx < CI_CHUNK * TH * TW; idx += NTHREADS) {
                int ci = idx >> 8;
                int r  = idx & 255;
                int yy = r >> 5;
                int xx = r & 31;
                s_in[ci][yy + 1][xx + 1] =
                    __ldg(in_x + (((size_t)b * CIN1 + sc0 + ci) * H_IMG + oy0 + yy) * W_IMG + ox0 + xx);
            }
            for (int idx = tid; idx < CI_CHUNK * COUT_T; idx += NTHREADS) {
                int co = idx >> 4;
                int ci = idx & 15;
                s_w[ci][0][co] = __ldg(scw + (size_t)(co0 + co) * CIN1 + sc0 + ci)
                                 * g_d2inv[b * COUT + co0 + co];
            }
            __syncthreads();
            #pragma unroll 1
            for (int ci = 0; ci < CI_CHUNK; ci++) {
                float4 wv = *(const float4*)&s_w[ci][0][cg4];
                const float* rowp = &s_in[ci][ty + 1][tx0 + 1];
                #pragma unroll
                for (int m = 0; m < 8; m++) {
                    float iv = rowp[m];
                    acc[m][0] += iv * wv.x;
                    acc[m][1] += iv * wv.y;
                    acc[m][2] += iv * wv.z;
                    acc[m][3] += iv * wv.w;
                }
            }
        }
    }

    // ---- epilogue ----
    const int gy  = oy0 + ty;
    const int gx0 = ox0 + tx0;
    const float nw = __ldg(noise_w);
    float nz[8];
    #pragma unroll
    for (int m = 0; m < 8; m++)
        nz[m] = nw * __ldg(noise + (size_t)b * (H_IMG * W_IMG) + gy * W_IMG + gx0 + m);

    #pragma unroll
    for (int j = 0; j < 4; j++) {
        int co = co0 + cg4 + j;
        float vv[8];
        if (FIRST) {
            float dm = g_d1[b * COUT + co];
            float st = g_style2[b * COUT + co];
            #pragma unroll
            for (int m = 0; m < 8; m++) {
                float v = dm * acc[m][j] + nz[m];
                vv[m] = lrelu(v) * st;
            }
        } else {
            float dm = g_d2[b * COUT + co];
            #pragma unroll
            for (int m = 0; m < 8; m++)
                vv[m] = (dm * acc[m][j] + nz[m]) * INV_SQRT2;
        }
        float* op = (FIRST ? (float*)g_t : out)
                    + ((size_t)b * COUT + co) * (H_IMG * W_IMG) + gy * W_IMG + gx0;
        *(float4*)(op)     = make_float4(vv[0], vv[1], vv[2], vv[3]);
        *(float4*)(op + 4) = make_float4(vv[4], vv[5], vv[6], vv[7]);
    }
}

// ---------------- launch ----------------
extern "C" void kernel_launch(void* const* d_in, const int* in_sizes, int n_in,
                              void* d_out, int out_size) {
    const float* x    = (const float*)d_in[0];
    const float* s    = (const float*)d_in[1];
    const float* noise= (const float*)d_in[2];
    const float* a1w  = (const float*)d_in[3];
    const float* a1b  = (const float*)d_in[4];
    const float* w1   = (const float*)d_in[5];
    const float* a2w  = (const float*)d_in[6];
    const float* a2b  = (const float*)d_in[7];
    const float* w2   = (const float*)d_in[8];
    const float* nw   = (const float*)d_in[9];
    const float* scw  = (const float*)d_in[10];
    float* out = (float*)d_out;

    precompute_kernel<<<BATCH, 128>>>(s, a1w, a1b, w1, a2w, a2b, w2);

    dim3 grid(W_IMG / TW, H_IMG / TH, BATCH * (COUT / COUT_T));
    conv3x3_kernel<CIN1, true><<<grid, NTHREADS>>>(x, w1, noise, nw, nullptr, nullptr);
    conv3x3_kernel<COUT, false><<<grid, NTHREADS>>>(x, w2, noise, nw, scw, out);
}

// round 3
// speedup vs baseline: 1.0011x; 1.0008x over previous
#include <cuda_runtime.h>
#include <cuda_bf16.h>
#include <cstdint>

#define H_IMG 256
#define W_IMG 256
#define BATCH 8
#define CIN1  64
#define COUT  128
#define SDIM  64

#define TW 32
#define TH 8
#define COUT_T 32
#define CI_CHUNK 16
#define NTHREADS 256

#define EPSV 1e-8f
#define INV_SQRT2 0.70710678118654752440f

// ---------------- scratch + precomputed small tensors ----------------
__device__ float g_t[(size_t)BATCH * COUT * H_IMG * W_IMG]; // 256 MB intermediate
__device__ float g_style1[BATCH * CIN1];
__device__ float g_style2[BATCH * COUT];
__device__ float g_d1[BATCH * COUT];
__device__ float g_d2[BATCH * COUT];
__device__ float g_d2inv[BATCH * COUT];

__device__ __forceinline__ float lrelu(float v) { return v > 0.f ? v : 0.2f * v; }

// ---------------- k0: styles + demod factors ----------------
__global__ void precompute_kernel(const float* __restrict__ s,
                                  const float* __restrict__ a1w, const float* __restrict__ a1b,
                                  const float* __restrict__ w1,
                                  const float* __restrict__ a2w, const float* __restrict__ a2b,
                                  const float* __restrict__ w2) {
    int b = blockIdx.x;
    int t = threadIdx.x;  // 0..127
    __shared__ float sh_s[SDIM];
    __shared__ float st1[CIN1];
    __shared__ float st2[COUT];

    if (t < SDIM) sh_s[t] = s[b * SDIM + t];
    __syncthreads();

    if (t < CIN1) {
        float acc = a1b[t];
        #pragma unroll 4
        for (int j = 0; j < SDIM; j++) acc += sh_s[j] * a1w[t * SDIM + j];
        acc += 1.0f;
        st1[t] = acc;
        g_style1[b * CIN1 + t] = acc;
    }
    {
        float acc = a2b[t];
        #pragma unroll 4
        for (int j = 0; j < SDIM; j++) acc += sh_s[j] * a2w[t * SDIM + j];
        acc += 1.0f;
        st2[t] = acc;
        g_style2[b * COUT + t] = acc;
    }
    __syncthreads();

    // d1[b][t] over w1 [128][64][9]
    {
        float sum = 0.f;
        for (int i = 0; i < CIN1; i++) {
            float wsq = 0.f;
            #pragma unroll
            for (int k = 0; k < 9; k++) { float wv = w1[(t * CIN1 + i) * 9 + k]; wsq += wv * wv; }
            float sv = st1[i];
            sum += wsq * sv * sv;
        }
        g_d1[b * COUT + t] = rsqrtf(sum + EPSV);
    }
    // d2[b][t] over w2 [128][128][9]
    {
        float sum = 0.f;
        for (int i = 0; i < COUT; i++) {
            float wsq = 0.f;
            #pragma unroll
            for (int k = 0; k < 9; k++) { float wv = w2[(t * COUT + i) * 9 + k]; wsq += wv * wv; }
            float sv = st2[i];
            sum += wsq * sv * sv;
        }
        float d = rsqrtf(sum + EPSV);
        g_d2[b * COUT + t] = d;
        g_d2inv[b * COUT + t] = 1.0f / d;
    }
}

// ---------------- fused 3x3 conv kernel ----------------
// FIRST:  in = x, apply lrelu+style1 on load; epilogue -> g_t = style2*lrelu(d1*acc + nw*noise)
// !FIRST: in = g_t; extra 1x1 shortcut (weights pre-divided by d2); epilogue ->
//         out = (d2*acc + nw*noise) * INV_SQRT2
template <int CIN, bool FIRST>
__global__ __launch_bounds__(NTHREADS)
void conv3x3_kernel(const float* __restrict__ in_x,       // x for FIRST / shortcut source for second
                    const float* __restrict__ w,
                    const float* __restrict__ noise,
                    const float* __restrict__ noise_w,
                    const float* __restrict__ scw,        // only used when !FIRST
                    float* __restrict__ out) {
    __shared__ __align__(16) float s_in[CI_CHUNK][TH + 2][36];
    __shared__ __align__(16) float s_w[CI_CHUNK][9][36];

    const int tid = threadIdx.x;
    const int cg  = tid & 7;        // 8 cout subgroups of 4
    const int cg4 = cg * 4;
    const int pt  = tid >> 3;       // 0..31
    const int ty  = pt >> 2;        // 0..7
    const int tx0 = (pt & 3) * 8;   // 0,8,16,24

    const int bz  = blockIdx.z;
    const int b   = bz >> 2;
    const int co0 = (bz & 3) * COUT_T;
    const int oy0 = blockIdx.y * TH;
    const int ox0 = blockIdx.x * TW;

    const float* inp = FIRST ? in_x : (const float*)g_t;

    float acc[8][4];
    #pragma unroll
    for (int m = 0; m < 8; m++)
        #pragma unroll
        for (int j = 0; j < 4; j++) acc[m][j] = 0.f;

    for (int ci0 = 0; ci0 < CIN; ci0 += CI_CHUNK) {
        __syncthreads();
        // ---- input tile (with halo) ----
        const float* in_b = inp + ((size_t)b * CIN + ci0) * (H_IMG * W_IMG);
        for (int idx = tid; idx < CI_CHUNK * 10 * 34; idx += NTHREADS) {
            int ci = idx / 340;
            int r  = idx - ci * 340;
            int yy = r / 34;
            int xx = r - yy * 34;
            int gy = oy0 - 1 + yy;
            int gx = ox0 - 1 + xx;
            float v = 0.f;
            if ((unsigned)gy < H_IMG && (unsigned)gx < W_IMG)
                v = __ldg(in_b + ci * (H_IMG * W_IMG) + gy * W_IMG + gx);
            if (FIRST) v = lrelu(v) * g_style1[b * CIN1 + ci0 + ci];
            s_in[ci][yy][xx] = v;
        }
        // ---- weights (coalesced over ci*9, 4-way STS conflict is negligible) ----
        const float* w_b = w + ((size_t)co0 * CIN + ci0) * 9;
        for (int idx = tid; idx < CI_CHUNK * 9 * COUT_T; idx += NTHREADS) {
            int co = idx / (CI_CHUNK * 9);
            int rk = idx - co * (CI_CHUNK * 9);   // ci*9 + k
            int ci = rk / 9;
            int k  = rk - ci * 9;
            s_w[ci][k][co] = __ldg(w_b + (size_t)co * CIN * 9 + rk);
        }
        __syncthreads();

        #pragma unroll 1
        for (int ci = 0; ci < CI_CHUNK; ci++) {
            #pragma unroll
            for (int kh = 0; kh < 3; kh++) {
                const float* row = &s_in[ci][ty + kh][tx0];
                float4 ra = *(const float4*)(row);
                float4 rb = *(const float4*)(row + 4);
                float2 rc = *(const float2*)(row + 8);
                float r[10] = {ra.x, ra.y, ra.z, ra.w, rb.x, rb.y, rb.z, rb.w, rc.x, rc.y};
                #pragma unroll
                for (int kw = 0; kw < 3; kw++) {
                    float4 wv = *(const float4*)&s_w[ci][kh * 3 + kw][cg4];
                    #pragma unroll
                    for (int m = 0; m < 8; m++) {
                        float iv = r[m + kw];
                        acc[m][0] += iv * wv.x;
                        acc[m][1] += iv * wv.y;
                        acc[m][2] += iv * wv.z;
                        acc[m][3] += iv * wv.w;
                    }
                }
            }
        }
    }

    if (!FIRST) {
        // ---- 1x1 learned shortcut on raw x, weights pre-scaled by 1/d2 ----
        for (int sc0 = 0; sc0 < CIN1; sc0 += CI_CHUNK) {
            __syncthreads();
            for (int idx = tid; idx < CI_CHUNK * TH * TW; idx += NTHREADS) {
                int ci = idx >> 8;
                int r  = idx & 255;
                int yy = r >> 5;
                int xx = r & 31;
                s_in[ci][yy + 1][xx + 1] =
                    __ldg(in_x + (((size_t)b * CIN1 + sc0 + ci) * H_IMG + oy0 + yy) * W_IMG + ox0 + xx);
            }
            for (int idx = tid; idx < CI_CHUNK * COUT_T; idx += NTHREADS) {
                int co = idx >> 4;
                int ci = idx & 15;
                s_w[ci][0][co] = __ldg(scw + (size_t)(co0 + co) * CIN1 + sc0 + ci)
                                 * g_d2inv[b * COUT + co0 + co];
            }
            __syncthreads();
            #pragma unroll 1
            for (int ci = 0; ci < CI_CHUNK; ci++) {
                float4 wv = *(const float4*)&s_w[ci][0][cg4];
                const float* rowp = &s_in[ci][ty + 1][tx0 + 1];
                #pragma unroll
                for (int m = 0; m < 8; m++) {
                    float iv = rowp[m];
                    acc[m][0] += iv * wv.x;
                    acc[m][1] += iv * wv.y;
                    acc[m][2] += iv * wv.z;
                    acc[m][3] += iv * wv.w;
                }
            }
        }
    }

    // ---- epilogue ----
    const int gy  = oy0 + ty;
    const int gx0 = ox0 + tx0;
    const float nw = __ldg(noise_w);
    float nz[8];
    #pragma unroll
    for (int m = 0; m < 8; m++)
        nz[m] = nw * __ldg(noise + (size_t)b * (H_IMG * W_IMG) + gy * W_IMG + gx0 + m);

    #pragma unroll
    for (int j = 0; j < 4; j++) {
        int co = co0 + cg4 + j;
        float vv[8];
        if (FIRST) {
            float dm = g_d1[b * COUT + co];
            float st = g_style2[b * COUT + co];
            #pragma unroll
            for (int m = 0; m < 8; m++) {
                float v = dm * acc[m][j] + nz[m];
                vv[m] = lrelu(v) * st;
            }
        } else {
            float dm = g_d2[b * COUT + co];
            #pragma unroll
            for (int m = 0; m < 8; m++)
                vv[m] = (dm * acc[m][j] + nz[m]) * INV_SQRT2;
        }
        float* op = (FIRST ? (float*)g_t : out)
                    + ((size_t)b * COUT + co) * (H_IMG * W_IMG) + gy * W_IMG + gx0;
        *(float4*)(op)     = make_float4(vv[0], vv[1], vv[2], vv[3]);
        *(float4*)(op + 4) = make_float4(vv[4], vv[5], vv[6], vv[7]);
    }
}

// ---------------- launch ----------------
extern "C" void kernel_launch(void* const* d_in, const int* in_sizes, int n_in,
                              void* d_out, int out_size) {
    const float* x    = (const float*)d_in[0];
    const float* s    = (const float*)d_in[1];
    const float* noise= (const float*)d_in[2];
    const float* a1w  = (const float*)d_in[3];
    const float* a1b  = (const float*)d_in[4];
    const float* w1   = (const float*)d_in[5];
    const float* a2w  = (const float*)d_in[6];
    const float* a2b  = (const float*)d_in[7];
    const float* w2   = (const float*)d_in[8];
    const float* nw   = (const float*)d_in[9];
    const float* scw  = (const float*)d_in[10];
    float* out = (float*)d_out;

    precompute_kernel<<<BATCH, 128>>>(s, a1w, a1b, w1, a2w, a2b, w2);

    dim3 grid(W_IMG / TW, H_IMG / TH, BATCH * (COUT / COUT_T));
    conv3x3_kernel<CIN1, true><<<grid, NTHREADS>>>(x, w1, noise, nw, nullptr, nullptr);
    conv3x3_kernel<COUT, false><<<grid, NTHREADS>>>(x, w2, noise, nw, scw, out);
}

// round 4
// speedup vs baseline: 2.1929x; 2.1904x over previous
#include <cuda_runtime.h>
#include <cstdint>

#define HW 256
#define BATCH 8
#define CIN1 64
#define COUT 128
#define SDIM 64
#define EPSV 1e-8f
#define INV_SQRT2 0.70710678118654752440f

__device__ float g_t[(size_t)BATCH * COUT * HW * HW];
__device__ float g_style1[BATCH * CIN1];
__device__ float g_style2[BATCH * COUT];
__device__ float g_d1[BATCH * COUT];
__device__ float g_d2[BATCH * COUT];
__device__ float g_d2inv[BATCH * COUT];
__device__ unsigned g_wp1[8 * 9216];
__device__ unsigned g_wp2[16 * 9216];

__device__ __forceinline__ float lrelu(float v) { return v > 0.f ? v : 0.2f * v; }

__device__ __forceinline__ unsigned f2tf32(float f) {
    unsigned u;
    asm("cvt.rna.tf32.f32 %0, %1;" : "=r"(u) : "f"(f));
    return u;
}

__device__ __forceinline__ void mma8(float c[4], unsigned a0, unsigned a1,
                                     unsigned a2, unsigned a3, unsigned b0, unsigned b1) {
    asm volatile(
        "mma.sync.aligned.m16n8k8.row.col.f32.tf32.tf32.f32 "
        "{%0,%1,%2,%3},{%4,%5,%6,%7},{%8,%9},{%0,%1,%2,%3};"
        : "+f"(c[0]), "+f"(c[1]), "+f"(c[2]), "+f"(c[3])
        : "r"(a0), "r"(a1), "r"(a2), "r"(a3), "r"(b0), "r"(b1));
}

__global__ void style_kernel(const float* __restrict__ s,
                             const float* __restrict__ a1w, const float* __restrict__ a1b,
                             const float* __restrict__ a2w, const float* __restrict__ a2b) {
    int b = blockIdx.x, t = threadIdx.x;
    __shared__ float sh[SDIM];
    if (t < SDIM) sh[t] = s[b * SDIM + t];
    __syncthreads();
    if (t < CIN1) {
        float a = a1b[t];
        #pragma unroll 4
        for (int j = 0; j < SDIM; j++) a += sh[j] * a1w[t * SDIM + j];
        g_style1[b * CIN1 + t] = a + 1.f;
    }
    float a = a2b[t];
    #pragma unroll 4
    for (int j = 0; j < SDIM; j++) a += sh[j] * a2w[t * SDIM + j];
    g_style2[b * COUT + t] = a + 1.f;
}

__global__ void demod_kernel(const float* __restrict__ w1, const float* __restrict__ w2) {
    int b = blockIdx.x;
    int co = blockIdx.y * 8 + (threadIdx.x >> 5);
    int lane = threadIdx.x & 31;
    float s1 = 0.f;
    for (int e = lane; e < CIN1 * 9; e += 32) {
        float wv = w1[co * CIN1 * 9 + e];
        float st = g_style1[b * CIN1 + e / 9];
        s1 += wv * wv * st * st;
    }
    #pragma unroll
    for (int o = 16; o; o >>= 1) s1 += __shfl_xor_sync(0xffffffffu, s1, o);
    if (lane == 0) g_d1[b * COUT + co] = rsqrtf(s1 + EPSV);
    float s2 = 0.f;
    for (int e = lane; e < COUT * 9; e += 32) {
        float wv = w2[co * COUT * 9 + e];
        float st = g_style2[b * COUT + e / 9];
        s2 += wv * wv * st * st;
    }
    #pragma unroll
    for (int o = 16; o; o >>= 1) s2 += __shfl_xor_sync(0xffffffffu, s2, o);
    if (lane == 0) {
        float d = rsqrtf(s2 + EPSV);
        g_d2[b * COUT + co] = d;
        g_d2inv[b * COUT + co] = 1.f / d;
    }
}

// weight prep: dst ((chunk*9+step)*128+co)*8 + j*2 + p ; k = step*8+j+4p ; k -> (ci,kh*3+kw)
template <bool FIRST>
__global__ void prep_weights(const float* __restrict__ w) {
    const int cin = FIRST ? CIN1 : COUT;
    unsigned* wp = FIRST ? g_wp1 : g_wp2;
    int idx = blockIdx.x * 256 + threadIdx.x;
    if (idx >= (cin / 8) * 9216) return;
    int c = idx / 9216, r = idx % 9216;
    int st = r >> 10, r2 = r & 1023;
    int co = r2 >> 3, j = (r2 >> 1) & 3, p = r2 & 1;
    int k = st * 8 + j + 4 * p;
    int ci = k / 9, rr = k - 9 * ci;
    wp[idx] = f2tf32(w[(co * cin + c * 8 + ci) * 9 + rr]);
}

// implicit-GEMM conv: CTA 128 px (8y x 16x) x 128 co
template <int CIN, bool FIRST>
__global__ __launch_bounds__(256, 2)
void conv_mma(const float* __restrict__ xin, const float* __restrict__ noise,
              const float* __restrict__ nwp, const float* __restrict__ scw,
              float* __restrict__ outp) {
    __shared__ __align__(16) unsigned s_in[1600];   // [8ci][10y][20x]
    __shared__ __align__(16) unsigned s_w[9216];    // [9 step][128 co][4 j][2 p]

    const int tid = threadIdx.x, lane = tid & 31, wrp = tid >> 5;
    const int wm = wrp & 3, wn = wrp >> 2;
    const int jj = lane & 3, pxl = lane >> 2;
    const int b = blockIdx.z;
    const int py0 = blockIdx.y * 8, px0 = blockIdx.x * 16;

    const float* src = FIRST ? xin : (const float*)g_t;
    const unsigned* wp = FIRST ? g_wp1 : g_wp2;

    float acc[2][8][4];
    #pragma unroll
    for (int m = 0; m < 2; m++)
        #pragma unroll
        for (int n = 0; n < 8; n++)
            #pragma unroll
            for (int q = 0; q < 4; q++) acc[m][n][q] = 0.f;

    for (int chk = 0; chk < CIN / 8; chk++) {
        __syncthreads();
        const int cib = chk * 8;
        for (int idx = tid; idx < 1440; idx += 256) {
            int ci = idx / 180, r = idx - ci * 180;
            int yy = r / 18, xx = r - yy * 18;
            int gy = py0 - 1 + yy, gx = px0 - 1 + xx;
            float v = 0.f;
            if ((unsigned)gy < HW && (unsigned)gx < HW)
                v = __ldg(src + (((size_t)b * CIN + cib + ci) * HW + gy) * HW + gx);
            if (FIRST) v = lrelu(v) * g_style1[b * CIN1 + cib + ci];
            s_in[ci * 200 + yy * 20 + xx] = f2tf32(v);
        }
        {
            const uint4* ws = (const uint4*)(wp + chk * 9216);
            uint4* wd = (uint4*)s_w;
            #pragma unroll
            for (int t2 = 0; t2 < 9; t2++) wd[tid + t2 * 256] = __ldg(ws + tid + t2 * 256);
        }
        __syncthreads();

        #pragma unroll
        for (int s = 0; s < 9; s++) {
            int klo = s * 8 + jj, khi = klo + 4;
            int cl = klo / 9, rl = klo - 9 * cl;
            int cm = khi / 9, rh = khi - 9 * cm;
            int off_lo = cl * 200 + (rl / 3) * 20 + (rl - 3 * (rl / 3));
            int off_hi = cm * 200 + (rh / 3) * 20 + (rh - 3 * (rh / 3));
            unsigned bvx[8], bvy[8];
            #pragma unroll
            for (int nf = 0; nf < 8; nf++) {
                uint2 t = *(const uint2*)&s_w[s * 1024 + (wn * 64 + nf * 8 + pxl) * 8 + jj * 2];
                bvx[nf] = t.x; bvy[nf] = t.y;
            }
            #pragma unroll
            for (int mf = 0; mf < 2; mf++) {
                int base = (2 * wm + mf) * 20 + pxl;
                unsigned a0 = s_in[base + off_lo];
                unsigned a1 = s_in[base + 8 + off_lo];
                unsigned a2 = s_in[base + off_hi];
                unsigned a3 = s_in[base + 8 + off_hi];
                #pragma unroll
                for (int nf = 0; nf < 8; nf++)
                    mma8(acc[mf][nf], a0, a1, a2, a3, bvx[nf], bvy[nf]);
            }
        }
    }

    if (!FIRST) {
        for (int chk = 0; chk < 8; chk++) {
            __syncthreads();
            const int cib = chk * 8;
            for (int idx = tid; idx < 1024; idx += 256) {
                int ci = idx >> 7, r = idx & 127;
                int yy = r >> 4, xx = r & 15;
                float v = __ldg(xin + (((size_t)b * CIN1 + cib + ci) * HW + py0 + yy) * HW + px0 + xx);
                s_in[ci * 200 + (yy + 1) * 20 + xx + 1] = f2tf32(v);
            }
            for (int idx = tid; idx < 1024; idx += 256) {
                int co = idx >> 3, j = (idx >> 1) & 3, p = idx & 1;
                float v = __ldg(scw + co * CIN1 + cib + j + 4 * p) * g_d2inv[b * COUT + co];
                s_w[co * 8 + j * 2 + p] = f2tf32(v);
            }
            __syncthreads();
            int off_lo = jj * 200 + 21;
            int off_hi = (jj + 4) * 200 + 21;
            unsigned bvx[8], bvy[8];
            #pragma unroll
            for (int nf = 0; nf < 8; nf++) {
                uint2 t = *(const uint2*)&s_w[(wn * 64 + nf * 8 + pxl) * 8 + jj * 2];
                bvx[nf] = t.x; bvy[nf] = t.y;
            }
            #pragma unroll
            for (int mf = 0; mf < 2; mf++) {
                int base = (2 * wm + mf) * 20 + pxl;
                unsigned a0 = s_in[base + off_lo];
                unsigned a1 = s_in[base + 8 + off_lo];
                unsigned a2 = s_in[base + off_hi];
                unsigned a3 = s_in[base + 8 + off_hi];
                #pragma unroll
                for (int nf = 0; nf < 8; nf++)
                    mma8(acc[mf][nf], a0, a1, a2, a3, bvx[nf], bvy[nf]);
            }
        }
    }

    // epilogue
    const float nw = __ldg(nwp);
    float nz[2][2];
    #pragma unroll
    for (int mf = 0; mf < 2; mf++) {
        int gy = py0 + 2 * wm + mf;
        const float* np = noise + (size_t)b * HW * HW + (size_t)gy * HW + px0 + pxl;
        nz[mf][0] = nw * __ldg(np);
        nz[mf][1] = nw * __ldg(np + 8);
    }
    float* obase = FIRST ? (float*)g_t : outp;
    #pragma unroll
    for (int nf = 0; nf < 8; nf++) {
        int coa = wn * 64 + nf * 8 + 2 * jj;
        int cob = coa + 1;
        float da, db, sa = 0.f, sb = 0.f;
        if (FIRST) {
            da = g_d1[b * COUT + coa]; db = g_d1[b * COUT + cob];
            sa = g_style2[b * COUT + coa]; sb = g_style2[b * COUT + cob];
        } else {
            da = g_d2[b * COUT + coa]; db = g_d2[b * COUT + cob];
        }
        #pragma unroll
        for (int mf = 0; mf < 2; mf++) {
            int gy = py0 + 2 * wm + mf;
            size_t pbase = (size_t)b * COUT * HW * HW + (size_t)gy * HW + px0 + pxl;
            float* pa = obase + pbase + (size_t)coa * (HW * HW);
            float* pb = obase + pbase + (size_t)cob * (HW * HW);
            float v0 = da * acc[mf][nf][0] + nz[mf][0];
            float v1 = db * acc[mf][nf][1] + nz[mf][0];
            float v2 = da * acc[mf][nf][2] + nz[mf][1];
            float v3 = db * acc[mf][nf][3] + nz[mf][1];
            if (FIRST) {
                pa[0] = lrelu(v0) * sa;
                pb[0] = lrelu(v1) * sb;
                pa[8] = lrelu(v2) * sa;
                pb[8] = lrelu(v3) * sb;
            } else {
                pa[0] = v0 * INV_SQRT2;
                pb[0] = v1 * INV_SQRT2;
                pa[8] = v2 * INV_SQRT2;
                pb[8] = v3 * INV_SQRT2;
            }
        }
    }
}

extern "C" void kernel_launch(void* const* d_in, const int* in_sizes, int n_in,
                              void* d_out, int out_size) {
    const float* x   = (const float*)d_in[0];
    const float* s   = (const float*)d_in[1];
    const float* noi = (const float*)d_in[2];
    const float* a1w = (const float*)d_in[3];
    const float* a1b = (const float*)d_in[4];
    const float* w1  = (const float*)d_in[5];
    const float* a2w = (const float*)d_in[6];
    const float* a2b = (const float*)d_in[7];
    const float* w2  = (const float*)d_in[8];
    const float* nw  = (const float*)d_in[9];
    const float* scw = (const float*)d_in[10];
    float* out = (float*)d_out;

    style_kernel<<<BATCH, 128>>>(s, a1w, a1b, a2w, a2b);
    demod_kernel<<<dim3(BATCH, 16), 256>>>(w1, w2);
    prep_weights<true><<<288, 256>>>(w1);
    prep_weights<false><<<576, 256>>>(w2);

    dim3 grid(HW / 16, HW / 8, BATCH);
    conv_mma<CIN1, true><<<grid, 256>>>(x, noi, nw, nullptr, nullptr);
    conv_mma<COUT, false><<<grid, 256>>>(x, noi, nw, scw, out);
}

// round 5
// speedup vs baseline: 3.7122x; 1.6928x over previous
#include <cuda_runtime.h>
#include <cstdint>

#define HW 256
#define BATCH 8
#define CIN1 64
#define COUT 128
#define SDIM 64
#define EPSV 1e-8f
#define INV_SQRT2 0.70710678118654752440f

__device__ float g_t[(size_t)BATCH * COUT * HW * HW];
__device__ float g_xact[(size_t)BATCH * CIN1 * HW * HW];
__device__ float g_style1[BATCH * CIN1];
__device__ float g_style2[BATCH * COUT];
__device__ float g_d1[BATCH * COUT];
__device__ float g_d2[BATCH * COUT];
__device__ float g_d2inv[BATCH * COUT];
__device__ unsigned g_wp1[8 * 9216];
__device__ unsigned g_wp2[16 * 9216];

#define BUF_WORDS 10816   // 1600 (s_in) + 9216 (s_w)
#define SMEM_BYTES (2 * BUF_WORDS * 4)

__device__ __forceinline__ float lrelu(float v) { return v > 0.f ? v : 0.2f * v; }

__device__ __forceinline__ unsigned f2tf32(float f) {
    unsigned u;
    asm("cvt.rna.tf32.f32 %0, %1;" : "=r"(u) : "f"(f));
    return u;
}

__device__ __forceinline__ void mma8(float c[4], unsigned a0, unsigned a1,
                                     unsigned a2, unsigned a3, unsigned b0, unsigned b1) {
    asm("mma.sync.aligned.m16n8k8.row.col.f32.tf32.tf32.f32 "
        "{%0,%1,%2,%3},{%4,%5,%6,%7},{%8,%9},{%0,%1,%2,%3};"
        : "+f"(c[0]), "+f"(c[1]), "+f"(c[2]), "+f"(c[3])
        : "r"(a0), "r"(a1), "r"(a2), "r"(a3), "r"(b0), "r"(b1));
}

__device__ __forceinline__ void cpa4z(uint32_t dst, const float* src, bool inb) {
    int sz = inb ? 4 : 0;
    asm volatile("cp.async.ca.shared.global [%0], [%1], 4, %2;"
                 :: "r"(dst), "l"(src), "r"(sz));
}
__device__ __forceinline__ void cpa16(uint32_t dst, const void* src) {
    asm volatile("cp.async.cg.shared.global [%0], [%1], 16;" :: "r"(dst), "l"(src));
}
__device__ __forceinline__ void cp_commit() { asm volatile("cp.async.commit_group;"); }
__device__ __forceinline__ void cp_wait0() { asm volatile("cp.async.wait_group 0;"); }

__global__ void style_kernel(const float* __restrict__ s,
                             const float* __restrict__ a1w, const float* __restrict__ a1b,
                             const float* __restrict__ a2w, const float* __restrict__ a2b) {
    int b = blockIdx.x, t = threadIdx.x;
    __shared__ float sh[SDIM];
    if (t < SDIM) sh[t] = s[b * SDIM + t];
    __syncthreads();
    if (t < CIN1) {
        float a = a1b[t];
        #pragma unroll 4
        for (int j = 0; j < SDIM; j++) a += sh[j] * a1w[t * SDIM + j];
        g_style1[b * CIN1 + t] = a + 1.f;
    }
    float a = a2b[t];
    #pragma unroll 4
    for (int j = 0; j < SDIM; j++) a += sh[j] * a2w[t * SDIM + j];
    g_style2[b * COUT + t] = a + 1.f;
}

__global__ void demod_kernel(const float* __restrict__ w1, const float* __restrict__ w2) {
    int b = blockIdx.x;
    int co = blockIdx.y * 8 + (threadIdx.x >> 5);
    int lane = threadIdx.x & 31;
    float s1 = 0.f;
    for (int e = lane; e < CIN1 * 9; e += 32) {
        float wv = w1[co * CIN1 * 9 + e];
        float st = g_style1[b * CIN1 + e / 9];
        s1 += wv * wv * st * st;
    }
    #pragma unroll
    for (int o = 16; o; o >>= 1) s1 += __shfl_xor_sync(0xffffffffu, s1, o);
    if (lane == 0) g_d1[b * COUT + co] = rsqrtf(s1 + EPSV);
    float s2 = 0.f;
    for (int e = lane; e < COUT * 9; e += 32) {
        float wv = w2[co * COUT * 9 + e];
        float st = g_style2[b * COUT + e / 9];
        s2 += wv * wv * st * st;
    }
    #pragma unroll
    for (int o = 16; o; o >>= 1) s2 += __shfl_xor_sync(0xffffffffu, s2, o);
    if (lane == 0) {
        float d = rsqrtf(s2 + EPSV);
        g_d2[b * COUT + co] = d;
        g_d2inv[b * COUT + co] = 1.f / d;
    }
}

// x_act = tf32_rna(lrelu(x) * style1)
__global__ void act_kernel(const float* __restrict__ x) {
    size_t i4 = (size_t)blockIdx.x * 256 + threadIdx.x;   // float4 index
    size_t total4 = (size_t)BATCH * CIN1 * HW * HW / 4;
    if (i4 >= total4) return;
    size_t base = i4 * 4;
    int bc = (int)(base >> 16);                 // b*64+ci
    int b = bc >> 6, ci = bc & 63;
    float st = g_style1[b * CIN1 + ci];
    float4 v = ((const float4*)x)[i4];
    uint4 o;
    o.x = f2tf32(lrelu(v.x) * st);
    o.y = f2tf32(lrelu(v.y) * st);
    o.z = f2tf32(lrelu(v.z) * st);
    o.w = f2tf32(lrelu(v.w) * st);
    ((uint4*)g_xact)[i4] = o;
}

template <bool FIRST>
__global__ void prep_weights(const float* __restrict__ w) {
    const int cin = FIRST ? CIN1 : COUT;
    unsigned* wp = FIRST ? g_wp1 : g_wp2;
    int idx = blockIdx.x * 256 + threadIdx.x;
    if (idx >= (cin / 8) * 9216) return;
    int c = idx / 9216, r = idx % 9216;
    int st = r >> 10, r2 = r & 1023;
    int co = r2 >> 3, j = (r2 >> 1) & 3, p = r2 & 1;
    int k = st * 8 + j + 4 * p;
    int ci = k / 9, rr = k - 9 * ci;
    wp[idx] = f2tf32(w[(co * cin + c * 8 + ci) * 9 + rr]);
}

// implicit-GEMM conv: CTA 128 px (8y x 16x) x 128 co, double-buffered cp.async
template <int CIN, bool FIRST>
__global__ __launch_bounds__(256, 2)
void conv_mma(const float* __restrict__ xin, const float* __restrict__ noise,
              const float* __restrict__ nwp, const float* __restrict__ scw,
              float* __restrict__ outp) {
    extern __shared__ __align__(16) unsigned smem[];

    const int tid = threadIdx.x, lane = tid & 31, wrp = tid >> 5;
    const int wm = wrp & 3, wn = wrp >> 2;
    const int jj = lane & 3, pxl = lane >> 2;
    const int b = blockIdx.z;
    const int py0 = blockIdx.y * 8, px0 = blockIdx.x * 16;

    const float* src = FIRST ? (const float*)g_xact : (const float*)g_t;
    const unsigned* wp = FIRST ? g_wp1 : g_wp2;
    const uint32_t smem_u32 = (uint32_t)__cvta_generic_to_shared(smem);

    float acc[2][8][4];
    #pragma unroll
    for (int m = 0; m < 2; m++)
        #pragma unroll
        for (int n = 0; n < 8; n++)
            #pragma unroll
            for (int q = 0; q < 4; q++) acc[m][n][q] = 0.f;

    const int CHUNKS = CIN / 8;

    // ---- async load of one chunk into buffer buf ----
    auto issue_chunk = [&](int chk, int buf) {
        uint32_t in_base = smem_u32 + (uint32_t)(buf * BUF_WORDS) * 4;
        uint32_t w_base  = in_base + 1600u * 4;
        const int cib = chk * 8;
        // input halo tile [8ci][10y][18x] (row pitch 20)
        #pragma unroll
        for (int t2 = 0; t2 < 6; t2++) {
            int idx = tid + t2 * 256;
            if (idx < 1440) {
                int ci = idx / 180, r = idx - ci * 180;
                int yy = r / 18, xx = r - yy * 18;
                int gy = py0 - 1 + yy, gx = px0 - 1 + xx;
                bool inb = ((unsigned)gy < HW) && ((unsigned)gx < HW);
                const float* sp = src + (((size_t)b * CIN + cib + ci) * HW + gy) * HW + gx;
                cpa4z(in_base + (uint32_t)(ci * 200 + yy * 20 + xx) * 4, sp, inb);
            }
        }
        // weights: straight 16B copies (pre-swizzled)
        const uint4* ws = (const uint4*)(wp + chk * 9216);
        #pragma unroll
        for (int t2 = 0; t2 < 9; t2++)
            cpa16(w_base + (uint32_t)(tid + t2 * 256) * 16, ws + tid + t2 * 256);
        cp_commit();
    };

    issue_chunk(0, 0);

    for (int chk = 0; chk < CHUNKS; chk++) {
        const int buf = chk & 1;
        cp_wait0();
        __syncthreads();
        if (chk + 1 < CHUNKS) issue_chunk(chk + 1, buf ^ 1);

        const unsigned* s_in = smem + buf * BUF_WORDS;
        const unsigned* s_w  = s_in + 1600;

        #pragma unroll
        for (int s = 0; s < 9; s++) {
            int klo = s * 8 + jj, khi = klo + 4;
            int cl = klo / 9, rl = klo - 9 * cl;
            int cm = khi / 9, rh = khi - 9 * cm;
            int off_lo = cl * 200 + (rl / 3) * 20 + (rl - 3 * (rl / 3));
            int off_hi = cm * 200 + (rh / 3) * 20 + (rh - 3 * (rh / 3));
            unsigned bvx[8], bvy[8];
            #pragma unroll
            for (int nf = 0; nf < 8; nf++) {
                uint2 t = *(const uint2*)&s_w[s * 1024 + (wn * 64 + nf * 8 + pxl) * 8 + jj * 2];
                bvx[nf] = t.x; bvy[nf] = t.y;
            }
            #pragma unroll
            for (int mf = 0; mf < 2; mf++) {
                int base = (2 * wm + mf) * 20 + pxl;
                unsigned a0 = s_in[base + off_lo];
                unsigned a1 = s_in[base + 8 + off_lo];
                unsigned a2 = s_in[base + off_hi];
                unsigned a3 = s_in[base + 8 + off_hi];
                #pragma unroll
                for (int nf = 0; nf < 8; nf++)
                    mma8(acc[mf][nf], a0, a1, a2, a3, bvx[nf], bvy[nf]);
            }
        }
        __syncthreads();
    }

    if (!FIRST) {
        unsigned* s_in = smem;           // reuse buffer 0
        unsigned* s_w  = smem + 1600;
        for (int chk = 0; chk < 8; chk++) {
            __syncthreads();
            const int cib = chk * 8;
            for (int idx = tid; idx < 1024; idx += 256) {
                int ci = idx >> 7, r = idx & 127;
                int yy = r >> 4, xx = r & 15;
                // raw fp32 bits as tf32 operand (HW truncation) — shortcut only
                s_in[ci * 200 + (yy + 1) * 20 + xx + 1] =
                    __float_as_uint(__ldg(xin + (((size_t)b * CIN1 + cib + ci) * HW + py0 + yy) * HW + px0 + xx));
            }
            for (int idx = tid; idx < 1024; idx += 256) {
                int co = idx >> 3, j = (idx >> 1) & 3, p = idx & 1;
                float v = __ldg(scw + co * CIN1 + cib + j + 4 * p) * g_d2inv[b * COUT + co];
                s_w[co * 8 + j * 2 + p] = f2tf32(v);
            }
            __syncthreads();
            int off_lo = jj * 200 + 21;
            int off_hi = (jj + 4) * 200 + 21;
            unsigned bvx[8], bvy[8];
            #pragma unroll
            for (int nf = 0; nf < 8; nf++) {
                uint2 t = *(const uint2*)&s_w[(wn * 64 + nf * 8 + pxl) * 8 + jj * 2];
                bvx[nf] = t.x; bvy[nf] = t.y;
            }
            #pragma unroll
            for (int mf = 0; mf < 2; mf++) {
                int base = (2 * wm + mf) * 20 + pxl;
                unsigned a0 = s_in[base + off_lo];
                unsigned a1 = s_in[base + 8 + off_lo];
                unsigned a2 = s_in[base + off_hi];
                unsigned a3 = s_in[base + 8 + off_hi];
                #pragma unroll
                for (int nf = 0; nf < 8; nf++)
                    mma8(acc[mf][nf], a0, a1, a2, a3, bvx[nf], bvy[nf]);
            }
        }
    }

    // epilogue
    const float nw = __ldg(nwp);
    float nz[2][2];
    #pragma unroll
    for (int mf = 0; mf < 2; mf++) {
        int gy = py0 + 2 * wm + mf;
        const float* np = noise + (size_t)b * HW * HW + (size_t)gy * HW + px0 + pxl;
        nz[mf][0] = nw * __ldg(np);
        nz[mf][1] = nw * __ldg(np + 8);
    }
    float* obase = FIRST ? (float*)g_t : outp;
    #pragma unroll
    for (int nf = 0; nf < 8; nf++) {
        int coa = wn * 64 + nf * 8 + 2 * jj;
        int cob = coa + 1;
        float da, db, sa = 0.f, sb = 0.f;
        if (FIRST) {
            da = g_d1[b * COUT + coa]; db = g_d1[b * COUT + cob];
            sa = g_style2[b * COUT + coa]; sb = g_style2[b * COUT + cob];
        } else {
            da = g_d2[b * COUT + coa]; db = g_d2[b * COUT + cob];
        }
        #pragma unroll
        for (int mf = 0; mf < 2; mf++) {
            int gy = py0 + 2 * wm + mf;
            size_t pbase = (size_t)b * COUT * HW * HW + (size_t)gy * HW + px0 + pxl;
            float* pa = obase + pbase + (size_t)coa * (HW * HW);
            float* pb = obase + pbase + (size_t)cob * (HW * HW);
            float v0 = da * acc[mf][nf][0] + nz[mf][0];
            float v1 = db * acc[mf][nf][1] + nz[mf][0];
            float v2 = da * acc[mf][nf][2] + nz[mf][1];
            float v3 = db * acc[mf][nf][3] + nz[mf][1];
            if (FIRST) {
                // store tf32-rounded so conv2's raw copies are exact RNA values
                pa[0] = __uint_as_float(f2tf32(lrelu(v0) * sa));
                pb[0] = __uint_as_float(f2tf32(lrelu(v1) * sb));
                pa[8] = __uint_as_float(f2tf32(lrelu(v2) * sa));
                pb[8] = __uint_as_float(f2tf32(lrelu(v3) * sb));
            } else {
                pa[0] = v0 * INV_SQRT2;
                pb[0] = v1 * INV_SQRT2;
                pa[8] = v2 * INV_SQRT2;
                pb[8] = v3 * INV_SQRT2;
            }
        }
    }
}

extern "C" void kernel_launch(void* const* d_in, const int* in_sizes, int n_in,
                              void* d_out, int out_size) {
    const float* x   = (const float*)d_in[0];
    const float* s   = (const float*)d_in[1];
    const float* noi = (const float*)d_in[2];
    const float* a1w = (const float*)d_in[3];
    const float* a1b = (const float*)d_in[4];
    const float* w1  = (const float*)d_in[5];
    const float* a2w = (const float*)d_in[6];
    const float* a2b = (const float*)d_in[7];
    const float* w2  = (const float*)d_in[8];
    const float* nw  = (const float*)d_in[9];
    const float* scw = (const float*)d_in[10];
    float* out = (float*)d_out;

    static bool attr_done = false;
    if (!attr_done) {
        cudaFuncSetAttribute(conv_mma<CIN1, true>,
                             cudaFuncAttributeMaxDynamicSharedMemorySize, SMEM_BYTES);
        cudaFuncSetAttribute(conv_mma<COUT, false>,
                             cudaFuncAttributeMaxDynamicSharedMemorySize, SMEM_BYTES);
        attr_done = true;
    }

    style_kernel<<<BATCH, 128>>>(s, a1w, a1b, a2w, a2b);
    demod_kernel<<<dim3(BATCH, 16), 256>>>(w1, w2);
    prep_weights<true><<<288, 256>>>(w1);
    prep_weights<false><<<576, 256>>>(w2);
    act_kernel<<<(BATCH * CIN1 * HW * HW / 4 + 255) / 256, 256>>>(x);

    dim3 grid(HW / 16, HW / 8, BATCH);
    conv_mma<CIN1, true><<<grid, 256, SMEM_BYTES>>>(x, noi, nw, nullptr, nullptr);
    conv_mma<COUT, false><<<grid, 256, SMEM_BYTES>>>(x, noi, nw, scw, out);
}

// round 8
// speedup vs baseline: 6.9770x; 1.8795x over previous
#include <cuda_runtime.h>
#include <cuda_fp16.h>
#include <cstdint>

#define HW 256
#define BATCH 8
#define EPSV 1e-8f
#define INV_SQRT2 0.70710678118654752440f

// ---------------- scratch (fp16 NHWC, channel-interleaved per 16) ----------------
__device__ __align__(1024) __half g_t[(size_t)BATCH * HW * HW * 128];
__device__ __align__(1024) __half g_xact[(size_t)BATCH * HW * HW * 64];
__device__ __align__(1024) __half g_xraw[(size_t)BATCH * HW * HW * 64];
__device__ __align__(1024) __half g_w1h[4 * 9 * 128 * 16];
__device__ __align__(1024) __half g_w2h[8 * 9 * 128 * 16];
__device__ __align__(1024) __half g_wsch[BATCH * 4 * 128 * 16];
__device__ float g_style1[BATCH * 64];
__device__ float g_style2[BATCH * 128];
__device__ float g_d1[BATCH * 128];
__device__ float g_d2[BATCH * 128];
__device__ float g_d2inv[BATCH * 128];

#define IN_WORDS 1440              // 180 px * 32B
#define W_WORDS 9216               // 9 taps * 128 co * 32B
#define BUF_WORDS (IN_WORDS + W_WORDS)
#define SMEM_BYTES (2 * BUF_WORDS * 4)

__device__ __forceinline__ float lrelu(float v) { return v > 0.f ? v : 0.2f * v; }
// storage index p (0..15) -> channel within 16-group
__device__ __forceinline__ int perm16(int p) {
    return 2 * (p >> 2) + (p & 1) + 8 * ((p >> 1) & 1);
}

__device__ __forceinline__ void mma16(float c[4], unsigned a0, unsigned a1,
                                      unsigned a2, unsigned a3, unsigned b0, unsigned b1) {
    asm("mma.sync.aligned.m16n8k16.row.col.f32.f16.f16.f32 "
        "{%0,%1,%2,%3},{%4,%5,%6,%7},{%8,%9},{%0,%1,%2,%3};"
        : "+f"(c[0]), "+f"(c[1]), "+f"(c[2]), "+f"(c[3])
        : "r"(a0), "r"(a1), "r"(a2), "r"(a3), "r"(b0), "r"(b1));
}

__device__ __forceinline__ void cpa16z(uint32_t dst, const void* src, bool inb) {
    int sz = inb ? 16 : 0;
    asm volatile("cp.async.ca.shared.global [%0], [%1], 16, %2;"
                 :: "r"(dst), "l"(src), "r"(sz));
}
__device__ __forceinline__ void cpa16(uint32_t dst, const void* src) {
    asm volatile("cp.async.cg.shared.global [%0], [%1], 16;" :: "r"(dst), "l"(src));
}
__device__ __forceinline__ void cp_commit() { asm volatile("cp.async.commit_group;"); }
__device__ __forceinline__ void cp_wait0() { asm volatile("cp.async.wait_group 0;"); }

// ---------------- small kernels ----------------
__global__ void style_kernel(const float* __restrict__ s,
                             const float* __restrict__ a1w, const float* __restrict__ a1b,
                             const float* __restrict__ a2w, const float* __restrict__ a2b) {
    int b = blockIdx.x, t = threadIdx.x;
    __shared__ float sh[64];
    if (t < 64) sh[t] = s[b * 64 + t];
    __syncthreads();
    if (t < 64) {
        float a = a1b[t];
        #pragma unroll 4
        for (int j = 0; j < 64; j++) a += sh[j] * a1w[t * 64 + j];
        g_style1[b * 64 + t] = a + 1.f;
    }
    float a = a2b[t];
    #pragma unroll 4
    for (int j = 0; j < 64; j++) a += sh[j] * a2w[t * 64 + j];
    g_style2[b * 128 + t] = a + 1.f;
}

__global__ void demod_kernel(const float* __restrict__ w1, const float* __restrict__ w2) {
    int b = blockIdx.x;
    int co = blockIdx.y * 8 + (threadIdx.x >> 5);
    int lane = threadIdx.x & 31;
    float s1 = 0.f;
    for (int e = lane; e < 64 * 9; e += 32) {
        float wv = w1[co * 64 * 9 + e];
        float st = g_style1[b * 64 + e / 9];
        s1 += wv * wv * st * st;
    }
    #pragma unroll
    for (int o = 16; o; o >>= 1) s1 += __shfl_xor_sync(0xffffffffu, s1, o);
    if (lane == 0) g_d1[b * 128 + co] = rsqrtf(s1 + EPSV);
    float s2 = 0.f;
    for (int e = lane; e < 128 * 9; e += 32) {
        float wv = w2[co * 128 * 9 + e];
        float st = g_style2[b * 128 + e / 9];
        s2 += wv * wv * st * st;
    }
    #pragma unroll
    for (int o = 16; o; o >>= 1) s2 += __shfl_xor_sync(0xffffffffu, s2, o);
    if (lane == 0) {
        float d = rsqrtf(s2 + EPSV);
        g_d2[b * 128 + co] = d;
        g_d2inv[b * 128 + co] = 1.f / d;
    }
}

// NCHW fp32 x -> NHWC fp16 (activated+styled, and raw), channel-permuted per 16
__global__ __launch_bounds__(256) void act_kernel(const float* __restrict__ x) {
    __shared__ float sa[64][65];
    __shared__ float sr[64][65];
    int t = threadIdx.x;
    int b = blockIdx.z, y = blockIdx.y, x0 = blockIdx.x * 64;
    {
        int ci = t >> 2, q = t & 3;
        const float* src = x + ((size_t)(b * 64 + ci) * 65536) + y * 256 + x0 + q * 16;
        float st = g_style1[b * 64 + ci];
        #pragma unroll
        for (int k = 0; k < 4; k++) {
            float4 v = *(const float4*)(src + k * 4);
            float rw[4] = {v.x, v.y, v.z, v.w};
            #pragma unroll
            for (int e = 0; e < 4; e++) {
                int xx = q * 16 + k * 4 + e;
                sr[ci][xx] = rw[e];
                sa[ci][xx] = lrelu(rw[e]) * st;
            }
        }
    }
    __syncthreads();
    int px = t >> 2, q = t & 3;   // q = 16-channel chunk
    size_t base = ((size_t)((b * 256 + y) * 256) + x0 + px) * 64 + q * 16;
    unsigned oa[8], orr[8];
    #pragma unroll
    for (int w = 0; w < 8; w++) {
        int ci0 = q * 16 + 2 * (w >> 1) + 8 * (w & 1);
        __half2 ha = __floats2half2_rn(sa[ci0][px], sa[ci0 + 1][px]);
        __half2 hr = __floats2half2_rn(sr[ci0][px], sr[ci0 + 1][px]);
        oa[w] = *(unsigned*)&ha;
        orr[w] = *(unsigned*)&hr;
    }
    *(uint4*)(g_xact + base)     = make_uint4(oa[0], oa[1], oa[2], oa[3]);
    *(uint4*)(g_xact + base + 8) = make_uint4(oa[4], oa[5], oa[6], oa[7]);
    *(uint4*)(g_xraw + base)     = make_uint4(orr[0], orr[1], orr[2], orr[3]);
    *(uint4*)(g_xraw + base + 8) = make_uint4(orr[4], orr[5], orr[6], orr[7]);
}

// weights -> [chunk][tap][co][p16] fp16 (ci permuted)
template <bool FIRST>
__global__ void prep_w(const float* __restrict__ w) {
    const int CIN = FIRST ? 64 : 128;
    int idx = blockIdx.x * 256 + threadIdx.x;
    if (idx >= (CIN / 16) * 9 * 128 * 16) return;
    int chk = idx / 18432, rem = idx % 18432;
    int tap = rem / 2048, rem2 = rem & 2047;
    int co = rem2 >> 4, p = rem2 & 15;
    int ci = chk * 16 + perm16(p);
    (FIRST ? g_w1h : g_w2h)[idx] = __float2half_rn(w[(co * CIN + ci) * 9 + tap]);
}

__global__ void prep_sc(const float* __restrict__ scw) {
    int idx = blockIdx.x * 256 + threadIdx.x;   // 65536
    int b = idx >> 13, rem = idx & 8191;
    int chk = rem >> 11;
    int co = (rem >> 4) & 127, p = rem & 15;
    int ci = chk * 16 + perm16(p);
    g_wsch[idx] = __float2half_rn(scw[co * 64 + ci] * g_d2inv[b * 128 + co]);
}

// ---------------- fp16 implicit-GEMM conv ----------------
// CTA: 128 px (8y x 16x) x 128 co. warp: 2y x 16x (32 px) x 64 co.
// K: per 16-ci chunk, 9 taps (k16 each).
template <int CIN, bool FIRST>
__global__ __launch_bounds__(256, 2)
void conv_fp16(const float* __restrict__ noise, const float* __restrict__ nwp,
               float* __restrict__ outp) {
    extern __shared__ __align__(16) unsigned smem[];
    const uint32_t smem_u32 = (uint32_t)__cvta_generic_to_shared(smem);

    const int tid = threadIdx.x, lane = tid & 31, wrp = tid >> 5;
    const int wm = wrp & 3, wn = wrp >> 2;
    const int j = lane & 3, r = lane >> 2;
    const int b = blockIdx.z;
    const int py0 = blockIdx.y * 8, px0 = blockIdx.x * 16;
    const int CCH = CIN / 16;

    const __half* src = FIRST ? g_xact : g_t;
    const __half* wsrc = FIRST ? g_w1h : g_w2h;

    float acc[2][8][4];
    #pragma unroll
    for (int m = 0; m < 2; m++)
        #pragma unroll
        for (int n = 0; n < 8; n++)
            #pragma unroll
            for (int q = 0; q < 4; q++) acc[m][n][q] = 0.f;

    auto issue = [&](int chk, int buf) {
        uint32_t in_base = smem_u32 + (uint32_t)(buf * BUF_WORDS) * 4;
        uint32_t w_base = in_base + IN_WORDS * 4;
        #pragma unroll
        for (int t2 = 0; t2 < 2; t2++) {
            int idx = tid + t2 * 256;
            if (idx < 360) {
                int half = idx & 1, pix = idx >> 1;
                int yy = pix / 18, xx = pix - yy * 18;
                int gy = py0 - 1 + yy, gx = px0 - 1 + xx;
                bool inb = ((unsigned)gy < HW) && ((unsigned)gx < HW);
                const __half* sp = src + (size_t)((b * 256 + gy) * 256 + gx) * CIN
                                   + chk * 16 + half * 8;
                cpa16z(in_base + (uint32_t)(pix * 32 + half * 16), sp, inb);
            }
        }
        const char* ws = (const char*)wsrc + (size_t)chk * 36864;
        #pragma unroll
        for (int t2 = 0; t2 < 9; t2++)
            cpa16(w_base + (uint32_t)(tid + t2 * 256) * 16, ws + (size_t)(tid + t2 * 256) * 16);
        cp_commit();
    };

    issue(0, 0);
    for (int chk = 0; chk < CCH; chk++) {
        const int buf = chk & 1;
        cp_wait0();
        __syncthreads();
        if (chk + 1 < CCH) issue(chk + 1, buf ^ 1);

        const unsigned* s_in = smem + buf * BUF_WORDS;
        const unsigned* s_w = s_in + IN_WORDS;

        #pragma unroll
        for (int tap = 0; tap < 9; tap++) {
            const int dy = tap / 3, dx = tap - 3 * dy;
            uint2 bv[8];
            #pragma unroll
            for (int nf = 0; nf < 8; nf++)
                bv[nf] = *(const uint2*)(s_w + (tap * 128 + wn * 64 + nf * 8 + r) * 8 + j * 2);
            #pragma unroll
            for (int mf = 0; mf < 2; mf++) {
                int pix1 = (2 * wm + mf + dy) * 18 + r + dx;
                uint2 alo = *(const uint2*)(s_in + pix1 * 8 + j * 2);
                uint2 ahi = *(const uint2*)(s_in + (pix1 + 8) * 8 + j * 2);
                #pragma unroll
                for (int nf = 0; nf < 8; nf++)
                    mma16(acc[mf][nf], alo.x, ahi.x, alo.y, ahi.y, bv[nf].x, bv[nf].y);
            }
        }
        __syncthreads();
    }

    if (!FIRST) {
        // 1x1 shortcut on raw x (fp16, permuted), weights pre-scaled by 1/d2
        const unsigned* s_in = smem;
        const unsigned* s_w = smem + 1024;
        uint32_t in_base = smem_u32, w_base = smem_u32 + 1024 * 4;
        for (int chk = 0; chk < 4; chk++) {
            __syncthreads();
            {
                int half = tid & 1, pix = tid >> 1;
                int yy = pix >> 4, xx = pix & 15;
                const __half* sp = g_xraw
                    + (size_t)((b * 256 + py0 + yy) * 256 + px0 + xx) * 64
                    + chk * 16 + half * 8;
                cpa16(in_base + (uint32_t)(pix * 32 + half * 16), sp);
                const char* ws = (const char*)g_wsch + (size_t)(b * 4 + chk) * 4096;
                cpa16(w_base + (uint32_t)tid * 16, ws + (size_t)tid * 16);
            }
            cp_commit();
            cp_wait0();
            __syncthreads();
            uint2 bv[8];
            #pragma unroll
            for (int nf = 0; nf < 8; nf++)
                bv[nf] = *(const uint2*)(s_w + (wn * 64 + nf * 8 + r) * 8 + j * 2);
            #pragma unroll
            for (int mf = 0; mf < 2; mf++) {
                int pix1 = (2 * wm + mf) * 16 + r;
                uint2 alo = *(const uint2*)(s_in + pix1 * 8 + j * 2);
                uint2 ahi = *(const uint2*)(s_in + (pix1 + 8) * 8 + j * 2);
                #pragma unroll
                for (int nf = 0; nf < 8; nf++)
                    mma16(acc[mf][nf], alo.x, ahi.x, alo.y, ahi.y, bv[nf].x, bv[nf].y);
            }
        }
    }

    // ---------------- epilogue ----------------
    const float nw = __ldg(nwp);
    float nz[2][2];
    #pragma unroll
    for (int mf = 0; mf < 2; mf++) {
        int gy = py0 + 2 * wm + mf;
        const float* np = noise + (size_t)b * 65536 + (size_t)gy * 256 + px0 + r;
        nz[mf][0] = nw * __ldg(np);
        nz[mf][1] = nw * __ldg(np + 8);
    }
    #pragma unroll
    for (int nf = 0; nf < 8; nf++) {
        int cp = wn * 64 + nf * 8 + 2 * j;       // even co of the pair
        float da, db, sa = 0.f, sb = 0.f;
        if (FIRST) {
            da = __ldg(g_d1 + b * 128 + cp); db = __ldg(g_d1 + b * 128 + cp + 1);
            sa = __ldg(g_style2 + b * 128 + cp); sb = __ldg(g_style2 + b * 128 + cp + 1);
        } else {
            da = __ldg(g_d2 + b * 128 + cp); db = __ldg(g_d2 + b * 128 + cp + 1);
        }
        #pragma unroll
        for (int mf = 0; mf < 2; mf++) {
            int gy = py0 + 2 * wm + mf;
            float v0 = da * acc[mf][nf][0] + nz[mf][0];
            float v1 = db * acc[mf][nf][1] + nz[mf][0];
            float v2 = da * acc[mf][nf][2] + nz[mf][1];
            float v3 = db * acc[mf][nf][3] + nz[mf][1];
            if (FIRST) {
                // write g_t NHWC fp16 (128 ch/px = 64 half2-words/px), permuted position
                int c16 = cp & 15;
                int word = 2 * ((c16 & 7) >> 1) + (c16 >> 3);   // half2-word within 16-group
                size_t pb = ((size_t)((b * 256 + gy) * 256) + px0 + r) * 64
                            + (cp >> 4) * 8 + word;
                __half2 h0 = __floats2half2_rn(lrelu(v0) * sa, lrelu(v1) * sb);
                __half2 h2 = __floats2half2_rn(lrelu(v2) * sa, lrelu(v3) * sb);
                *(__half2*)((__half*)g_t + pb * 2) = h0;
                *(__half2*)((__half*)g_t + (pb + 8 * 64) * 2) = h2;   // x+8 -> +8 px * 64 words
            } else {
                size_t ob = ((size_t)(b * 128 + cp) * 256 + gy) * 256 + px0 + r;
                outp[ob] = v0 * INV_SQRT2;
                outp[ob + 65536] = v1 * INV_SQRT2;        // co+1
                outp[ob + 8] = v2 * INV_SQRT2;            // x+8
                outp[ob + 65536 + 8] = v3 * INV_SQRT2;
            }
        }
    }
}

// ---------------- host ----------------
extern "C" void kernel_launch(void* const* d_in, const int* in_sizes, int n_in,
                              void* d_out, int out_size) {
    const float* x   = (const float*)d_in[0];
    const float* s   = (const float*)d_in[1];
    const float* noi = (const float*)d_in[2];
    const float* a1w = (const float*)d_in[3];
    const float* a1b = (const float*)d_in[4];
    const float* w1  = (const float*)d_in[5];
    const float* a2w = (const float*)d_in[6];
    const float* a2b = (const float*)d_in[7];
    const float* w2  = (const float*)d_in[8];
    const float* nw  = (const float*)d_in[9];
    const float* scw = (const float*)d_in[10];
    float* out = (float*)d_out;

    static bool attr_done = false;
    if (!attr_done) {
        cudaFuncSetAttribute(conv_fp16<64, true>,
                             cudaFuncAttributeMaxDynamicSharedMemorySize, SMEM_BYTES);
        cudaFuncSetAttribute(conv_fp16<128, false>,
                             cudaFuncAttributeMaxDynamicSharedMemorySize, SMEM_BYTES);
        attr_done = true;
    }

    style_kernel<<<BATCH, 128>>>(s, a1w, a1b, a2w, a2b);
    demod_kernel<<<dim3(BATCH, 16), 256>>>(w1, w2);
    prep_w<true><<<288, 256>>>(w1);
    prep_w<false><<<576, 256>>>(w2);
    prep_sc<<<256, 256>>>(scw);
    act_kernel<<<dim3(4, 256, 8), 256>>>(x);

    dim3 grid(HW / 16, HW / 8, BATCH);
    conv_fp16<64, true><<<grid, 256, SMEM_BYTES>>>(noi, nw, nullptr);
    conv_fp16<128, false><<<grid, 256, SMEM_BYTES>>>(noi, nw, out);
}